// round 4
// baseline (speedup 1.0000x reference)
#include <cuda_runtime.h>

#define BB 4
#define CC 64
#define HH 128
#define WW 128
#define GG 16
#define KK 7
#define CRR 16
#define HW (HH*WW)            // 16384
#define CHW (CC*HW)           // 1048576
#define NPIX (BB*HW)          // 65536
#define STAT_BLOCKS 256

// Scratch (device globals: allocation-guard safe)
__device__ float g_dw[BB*CHW];            // depthwise output, 16MB
__device__ float g_h [BB*CHW];            // pointwise output (involution "features"), 16MB
__device__ float g_r [BB*CRR*HW];         // reduce output (pre-BN), 4MB
__device__ float g_psum[CRR*STAT_BLOCKS];
__device__ float g_psq [CRR*STAT_BLOCKS];
__device__ float g_scale[CRR];
__device__ float g_bias [CRR];

// ---------------------------------------------------------------------------
// Kernel A: depthwise 3x3 conv, pad 1. One thread = one float4 quad of pixels.
// ---------------------------------------------------------------------------
__global__ void k_dw(const float* __restrict__ x, const float* __restrict__ wdw) {
    int t = blockIdx.x * blockDim.x + threadIdx.x;   // 0 .. 1048575
    int xq = t & 31;            // quad index in row (32 quads of 4)
    int y  = (t >> 5) & 127;
    int c  = (t >> 12) & 63;
    int b  = t >> 18;

    float w[9];
    const float* wp = wdw + c * 9;
#pragma unroll
    for (int i = 0; i < 9; i++) w[i] = __ldg(wp + i);

    float a0 = 0.f, a1 = 0.f, a2 = 0.f, a3 = 0.f;
    const float* base = x + (size_t)(b * 64 + c) * HW;
    int x0 = xq * 4;
#pragma unroll
    for (int dy = -1; dy <= 1; dy++) {
        int yy = y + dy;
        if (yy < 0 || yy >= HH) continue;
        const float* row = base + yy * WW;
        float v[6];
#pragma unroll
        for (int j = 0; j < 6; j++) {
            int xx = x0 - 1 + j;
            v[j] = (xx >= 0 && xx < WW) ? row[xx] : 0.f;
        }
#pragma unroll
        for (int kx = 0; kx < 3; kx++) {
            float wv = w[(dy + 1) * 3 + kx];
            a0 = fmaf(wv, v[kx + 0], a0);
            a1 = fmaf(wv, v[kx + 1], a1);
            a2 = fmaf(wv, v[kx + 2], a2);
            a3 = fmaf(wv, v[kx + 3], a3);
        }
    }
    float4* dst = (float4*)(g_dw + (size_t)(b * 64 + c) * HW + y * WW + x0);
    *dst = make_float4(a0, a1, a2, a3);
}

// ---------------------------------------------------------------------------
// Kernel B: pointwise 1x1, 64->64. Thread = (pixel quad, chunk of 16 outputs).
// grid (64, 4), block 256. Weights staged in shared.
// ---------------------------------------------------------------------------
__global__ void k_pw(const float* __restrict__ wpw) {
    __shared__ float wsh[64 * 64];
    int tid = threadIdx.x;
    for (int i = tid; i < 4096; i += 256) wsh[i] = wpw[i];
    __syncthreads();

    int quad = blockIdx.x * 256 + tid;    // 0..16383
    int oc0  = blockIdx.y * 16;           // output channel base
    int b  = quad >> 12;                  // 4096 quads per image
    int p4 = (quad & 4095) * 4;

    const float* src = g_dw + (size_t)b * CHW + p4;

    float4 acc[16];
#pragma unroll
    for (int o = 0; o < 16; o++) acc[o] = make_float4(0.f, 0.f, 0.f, 0.f);

#pragma unroll 4
    for (int c4 = 0; c4 < 16; c4++) {
        float4 v0 = *(const float4*)(src + (c4 * 4 + 0) * HW);
        float4 v1 = *(const float4*)(src + (c4 * 4 + 1) * HW);
        float4 v2 = *(const float4*)(src + (c4 * 4 + 2) * HW);
        float4 v3 = *(const float4*)(src + (c4 * 4 + 3) * HW);
#pragma unroll
        for (int o = 0; o < 16; o++) {
            float4 wv = *(const float4*)&wsh[(oc0 + o) * 64 + c4 * 4];
            acc[o].x = fmaf(wv.x, v0.x, fmaf(wv.y, v1.x, fmaf(wv.z, v2.x, fmaf(wv.w, v3.x, acc[o].x))));
            acc[o].y = fmaf(wv.x, v0.y, fmaf(wv.y, v1.y, fmaf(wv.z, v2.y, fmaf(wv.w, v3.y, acc[o].y))));
            acc[o].z = fmaf(wv.x, v0.z, fmaf(wv.y, v1.z, fmaf(wv.z, v2.z, fmaf(wv.w, v3.z, acc[o].z))));
            acc[o].w = fmaf(wv.x, v0.w, fmaf(wv.y, v1.w, fmaf(wv.z, v2.w, fmaf(wv.w, v3.w, acc[o].w))));
        }
    }
#pragma unroll
    for (int o = 0; o < 16; o++)
        *(float4*)(g_h + (size_t)b * CHW + (oc0 + o) * HW + p4) = acc[o];
}

// ---------------------------------------------------------------------------
// Kernel C: reduce 64->16 (r) + deterministic per-block BN partial stats.
// One thread per pixel. grid 256, block 256.
// ---------------------------------------------------------------------------
__global__ void k_reduce(const float* __restrict__ x, const float* __restrict__ wred) {
    __shared__ float wt[64 * 16];         // transposed: wt[c*16 + cr]
    __shared__ float sm_s[16][8];
    __shared__ float sm_q[16][8];
    int tid = threadIdx.x;
    for (int i = tid; i < 1024; i += 256) {
        int cr = i >> 6, c = i & 63;
        wt[c * 16 + cr] = wred[i];
    }
    __syncthreads();

    int pix = blockIdx.x * 256 + tid;     // 0..65535
    int b = pix >> 14;
    int p = pix & 16383;
    const float* src = x + (size_t)b * CHW + p;

    float acc[16];
#pragma unroll
    for (int i = 0; i < 16; i++) acc[i] = 0.f;

    for (int c = 0; c < 64; c++) {
        float v = src[c * HW];
        const float4* w4 = (const float4*)&wt[c * 16];
        float4 w0 = w4[0], w1 = w4[1], w2 = w4[2], w3 = w4[3];
        acc[0]  = fmaf(w0.x, v, acc[0]);  acc[1]  = fmaf(w0.y, v, acc[1]);
        acc[2]  = fmaf(w0.z, v, acc[2]);  acc[3]  = fmaf(w0.w, v, acc[3]);
        acc[4]  = fmaf(w1.x, v, acc[4]);  acc[5]  = fmaf(w1.y, v, acc[5]);
        acc[6]  = fmaf(w1.z, v, acc[6]);  acc[7]  = fmaf(w1.w, v, acc[7]);
        acc[8]  = fmaf(w2.x, v, acc[8]);  acc[9]  = fmaf(w2.y, v, acc[9]);
        acc[10] = fmaf(w2.z, v, acc[10]); acc[11] = fmaf(w2.w, v, acc[11]);
        acc[12] = fmaf(w3.x, v, acc[12]); acc[13] = fmaf(w3.y, v, acc[13]);
        acc[14] = fmaf(w3.z, v, acc[14]); acc[15] = fmaf(w3.w, v, acc[15]);
    }

    float* rdst = g_r + (size_t)b * (CRR * HW) + p;
#pragma unroll
    for (int cr = 0; cr < 16; cr++) rdst[cr * HW] = acc[cr];

    // deterministic block reduction of sum / sumsq per channel
    int lane = tid & 31, warp = tid >> 5;
#pragma unroll
    for (int cr = 0; cr < 16; cr++) {
        float s = acc[cr];
        float q = acc[cr] * acc[cr];
#pragma unroll
        for (int off = 16; off; off >>= 1) {
            s += __shfl_down_sync(0xFFFFFFFFu, s, off);
            q += __shfl_down_sync(0xFFFFFFFFu, q, off);
        }
        if (lane == 0) { sm_s[cr][warp] = s; sm_q[cr][warp] = q; }
    }
    __syncthreads();
    if (tid < 16) {
        float s = 0.f, q = 0.f;
#pragma unroll
        for (int w = 0; w < 8; w++) { s += sm_s[tid][w]; q += sm_q[tid][w]; }
        g_psum[tid * STAT_BLOCKS + blockIdx.x] = s;
        g_psq [tid * STAT_BLOCKS + blockIdx.x] = q;
    }
}

// ---------------------------------------------------------------------------
// Kernel D: finalize BN stats -> scale/bias. 1 block, 16 warps (one per cr).
// ---------------------------------------------------------------------------
__global__ void k_bnstats(const float* __restrict__ gamma, const float* __restrict__ beta) {
    int w = threadIdx.x >> 5;     // cr
    int lane = threadIdx.x & 31;
    float s = 0.f, q = 0.f;
    for (int i = lane; i < STAT_BLOCKS; i += 32) {
        s += g_psum[w * STAT_BLOCKS + i];
        q += g_psq [w * STAT_BLOCKS + i];
    }
#pragma unroll
    for (int off = 16; off; off >>= 1) {
        s += __shfl_down_sync(0xFFFFFFFFu, s, off);
        q += __shfl_down_sync(0xFFFFFFFFu, q, off);
    }
    if (lane == 0) {
        const float inv = 1.0f / (float)NPIX;
        float mean = s * inv;
        float var  = q * inv - mean * mean;
        float sc = gamma[w] * rsqrtf(var + 1e-5f);
        g_scale[w] = sc;
        g_bias[w]  = beta[w] - mean * sc;
    }
}

// ---------------------------------------------------------------------------
// Kernel E: fused BN+ReLU -> span GEMM (kern gen) -> involution (49 taps x 4 ch).
// grid (8, 8, B*G), block 256 (16x16 tile). h tile (4 ch packed float4) in shared.
// ---------------------------------------------------------------------------
__global__ __launch_bounds__(256, 2) void k_main(const float* __restrict__ wspan,
                                                 float* __restrict__ out) {
    __shared__ float4 hsh[22 * 22];
    __shared__ float  wsp[49 * 16];
    __shared__ float  ssc[16], sbi[16];

    int tid = threadIdx.x;
    int b = blockIdx.z >> 4;
    int g = blockIdx.z & 15;

    // stage span weights for this group
    const float* wsrc = wspan + g * 49 * 16;
    for (int i = tid; i < 784; i += 256) wsp[i] = wsrc[i];
    if (tid < 16) { ssc[tid] = g_scale[tid]; sbi[tid] = g_bias[tid]; }

    // stage h tile (4 channels of this group, packed) with halo 3
    int y0 = blockIdx.y * 16 - 3, x0 = blockIdx.x * 16 - 3;
    const float* hb = g_h + (size_t)b * CHW + (g * 4) * HW;
    for (int i = tid; i < 484; i += 256) {
        int ly = i / 22, lx = i - ly * 22;
        int yy = y0 + ly, xx = x0 + lx;
        float4 v = make_float4(0.f, 0.f, 0.f, 0.f);
        if ((unsigned)yy < (unsigned)HH && (unsigned)xx < (unsigned)WW) {
            int off = yy * WW + xx;
            v.x = hb[off];
            v.y = hb[off + HW];
            v.z = hb[off + 2 * HW];
            v.w = hb[off + 3 * HW];
        }
        hsh[i] = v;
    }
    __syncthreads();

    int ty = tid >> 4, tx = tid & 15;
    int y = blockIdx.y * 16 + ty, x = blockIdx.x * 16 + tx;

    // normalized + ReLU'd r for this pixel
    const float* rb = g_r + (size_t)b * (CRR * HW) + y * WW + x;
    float rn[16];
#pragma unroll
    for (int cr = 0; cr < 16; cr++)
        rn[cr] = fmaxf(fmaf(rb[cr * HW], ssc[cr], sbi[cr]), 0.f);

    // kernel generation: kern[kk] = sum_cr wsp[kk][cr] * rn[cr]
    float kern[49];
#pragma unroll
    for (int kk = 0; kk < 49; kk++) {
        const float4* w4 = (const float4*)&wsp[kk * 16];
        float4 w0 = w4[0], w1 = w4[1], w2 = w4[2], w3 = w4[3];
        float s;
        s = w0.x * rn[0];
        s = fmaf(w0.y, rn[1],  s);
        s = fmaf(w0.z, rn[2],  s);
        s = fmaf(w0.w, rn[3],  s);
        s = fmaf(w1.x, rn[4],  s);
        s = fmaf(w1.y, rn[5],  s);
        s = fmaf(w1.z, rn[6],  s);
        s = fmaf(w1.w, rn[7],  s);
        s = fmaf(w2.x, rn[8],  s);
        s = fmaf(w2.y, rn[9],  s);
        s = fmaf(w2.z, rn[10], s);
        s = fmaf(w2.w, rn[11], s);
        s = fmaf(w3.x, rn[12], s);
        s = fmaf(w3.y, rn[13], s);
        s = fmaf(w3.z, rn[14], s);
        s = fmaf(w3.w, rn[15], s);
        kern[kk] = s;
    }

    // involution: 49 taps x 4 channels (float4 packed)
    float ax = 0.f, ay = 0.f, az = 0.f, aw = 0.f;
#pragma unroll
    for (int ky = 0; ky < 7; ky++) {
#pragma unroll
        for (int kx = 0; kx < 7; kx++) {
            float4 hv = hsh[(ty + ky) * 22 + (tx + kx)];
            float kw = kern[ky * 7 + kx];
            ax = fmaf(kw, hv.x, ax);
            ay = fmaf(kw, hv.y, ay);
            az = fmaf(kw, hv.z, az);
            aw = fmaf(kw, hv.w, aw);
        }
    }

    float* ob = out + (size_t)b * CHW + (g * 4) * HW + y * WW + x;
    ob[0]      = ax;
    ob[HW]     = ay;
    ob[2 * HW] = az;
    ob[3 * HW] = aw;
}

// ---------------------------------------------------------------------------
extern "C" void kernel_launch(void* const* d_in, const int* in_sizes, int n_in,
                              void* d_out, int out_size) {
    const float* x      = (const float*)d_in[0];   // input  [4,64,128,128]
    const float* w_dw   = (const float*)d_in[1];   // [64,1,3,3]
    const float* w_pw   = (const float*)d_in[2];   // [64,64]
    const float* gamma  = (const float*)d_in[3];   // [16]
    const float* beta   = (const float*)d_in[4];   // [16]
    const float* w_red  = (const float*)d_in[5];   // [16,64]
    const float* w_span = (const float*)d_in[6];   // [784,16]
    float* out = (float*)d_out;

    k_dw<<<4096, 256>>>(x, w_dw);
    k_pw<<<dim3(64, 4), 256>>>(w_pw);
    k_reduce<<<STAT_BLOCKS, 256>>>(x, w_red);
    k_bnstats<<<1, 512>>>(gamma, beta);
    k_main<<<dim3(8, 8, BB * GG), 256>>>(w_span, out);
}

// round 5
// speedup vs baseline: 1.5644x; 1.5644x over previous
#include <cuda_runtime.h>

#define BB 4
#define CC 64
#define HH 128
#define WW 128
#define GG 16
#define KK 7
#define CRR 16
#define HW (HH*WW)            // 16384
#define CHW (CC*HW)           // 1048576
#define NPIX (BB*HW)          // 65536
#define STAT_BLOCKS 256

// Scratch (device globals: allocation-guard safe)
__device__ float g_dw[BB*CHW];            // depthwise output, 16MB
__device__ float g_h [BB*CHW];            // pointwise output (involution "features"), 16MB
__device__ float g_r [BB*CRR*HW];         // reduce output (pre-BN), 4MB
__device__ float g_psum[CRR*STAT_BLOCKS];
__device__ float g_psq [CRR*STAT_BLOCKS];
__device__ float g_scale[CRR];
__device__ float g_bias [CRR];

// ---------------------------------------------------------------------------
// Kernel A: depthwise 3x3 conv, pad 1. One thread = one float4 quad of pixels.
// ---------------------------------------------------------------------------
__global__ void k_dw(const float* __restrict__ x, const float* __restrict__ wdw) {
    int t = blockIdx.x * blockDim.x + threadIdx.x;   // 0 .. 1048575
    int xq = t & 31;            // quad index in row (32 quads of 4)
    int y  = (t >> 5) & 127;
    int c  = (t >> 12) & 63;
    int b  = t >> 18;

    float w[9];
    const float* wp = wdw + c * 9;
#pragma unroll
    for (int i = 0; i < 9; i++) w[i] = __ldg(wp + i);

    float a0 = 0.f, a1 = 0.f, a2 = 0.f, a3 = 0.f;
    const float* base = x + (size_t)(b * 64 + c) * HW;
    int x0 = xq * 4;
#pragma unroll
    for (int dy = -1; dy <= 1; dy++) {
        int yy = y + dy;
        if (yy < 0 || yy >= HH) continue;
        const float* row = base + yy * WW;
        float v[6];
#pragma unroll
        for (int j = 0; j < 6; j++) {
            int xx = x0 - 1 + j;
            v[j] = (xx >= 0 && xx < WW) ? row[xx] : 0.f;
        }
#pragma unroll
        for (int kx = 0; kx < 3; kx++) {
            float wv = w[(dy + 1) * 3 + kx];
            a0 = fmaf(wv, v[kx + 0], a0);
            a1 = fmaf(wv, v[kx + 1], a1);
            a2 = fmaf(wv, v[kx + 2], a2);
            a3 = fmaf(wv, v[kx + 3], a3);
        }
    }
    float4* dst = (float4*)(g_dw + (size_t)(b * 64 + c) * HW + y * WW + x0);
    *dst = make_float4(a0, a1, a2, a3);
}

// ---------------------------------------------------------------------------
// Kernel B: pointwise 1x1, 64->64. Thread = (pixel quad, chunk of 16 outputs).
// grid (64, 4), block 256. Weights staged in shared.
// ---------------------------------------------------------------------------
__global__ void k_pw(const float* __restrict__ wpw) {
    __shared__ float wsh[64 * 64];
    int tid = threadIdx.x;
    for (int i = tid; i < 4096; i += 256) wsh[i] = wpw[i];
    __syncthreads();

    int quad = blockIdx.x * 256 + tid;    // 0..16383
    int oc0  = blockIdx.y * 16;           // output channel base
    int b  = quad >> 12;                  // 4096 quads per image
    int p4 = (quad & 4095) * 4;

    const float* src = g_dw + (size_t)b * CHW + p4;

    float4 acc[16];
#pragma unroll
    for (int o = 0; o < 16; o++) acc[o] = make_float4(0.f, 0.f, 0.f, 0.f);

#pragma unroll 4
    for (int c4 = 0; c4 < 16; c4++) {
        float4 v0 = *(const float4*)(src + (c4 * 4 + 0) * HW);
        float4 v1 = *(const float4*)(src + (c4 * 4 + 1) * HW);
        float4 v2 = *(const float4*)(src + (c4 * 4 + 2) * HW);
        float4 v3 = *(const float4*)(src + (c4 * 4 + 3) * HW);
#pragma unroll
        for (int o = 0; o < 16; o++) {
            float4 wv = *(const float4*)&wsh[(oc0 + o) * 64 + c4 * 4];
            acc[o].x = fmaf(wv.x, v0.x, fmaf(wv.y, v1.x, fmaf(wv.z, v2.x, fmaf(wv.w, v3.x, acc[o].x))));
            acc[o].y = fmaf(wv.x, v0.y, fmaf(wv.y, v1.y, fmaf(wv.z, v2.y, fmaf(wv.w, v3.y, acc[o].y))));
            acc[o].z = fmaf(wv.x, v0.z, fmaf(wv.y, v1.z, fmaf(wv.z, v2.z, fmaf(wv.w, v3.z, acc[o].z))));
            acc[o].w = fmaf(wv.x, v0.w, fmaf(wv.y, v1.w, fmaf(wv.z, v2.w, fmaf(wv.w, v3.w, acc[o].w))));
        }
    }
#pragma unroll
    for (int o = 0; o < 16; o++)
        *(float4*)(g_h + (size_t)b * CHW + (oc0 + o) * HW + p4) = acc[o];
}

// ---------------------------------------------------------------------------
// Kernel C: reduce 64->16 (r) + deterministic per-block BN partial stats.
// One thread per pixel. grid 256, block 256.
// ---------------------------------------------------------------------------
__global__ void k_reduce(const float* __restrict__ x, const float* __restrict__ wred) {
    __shared__ float wt[64 * 16];         // transposed: wt[c*16 + cr]
    __shared__ float sm_s[16][8];
    __shared__ float sm_q[16][8];
    int tid = threadIdx.x;
    for (int i = tid; i < 1024; i += 256) {
        int cr = i >> 6, c = i & 63;
        wt[c * 16 + cr] = wred[i];
    }
    __syncthreads();

    int pix = blockIdx.x * 256 + tid;     // 0..65535
    int b = pix >> 14;
    int p = pix & 16383;
    const float* src = x + (size_t)b * CHW + p;

    float acc[16];
#pragma unroll
    for (int i = 0; i < 16; i++) acc[i] = 0.f;

    for (int c = 0; c < 64; c++) {
        float v = src[c * HW];
        const float4* w4 = (const float4*)&wt[c * 16];
        float4 w0 = w4[0], w1 = w4[1], w2 = w4[2], w3 = w4[3];
        acc[0]  = fmaf(w0.x, v, acc[0]);  acc[1]  = fmaf(w0.y, v, acc[1]);
        acc[2]  = fmaf(w0.z, v, acc[2]);  acc[3]  = fmaf(w0.w, v, acc[3]);
        acc[4]  = fmaf(w1.x, v, acc[4]);  acc[5]  = fmaf(w1.y, v, acc[5]);
        acc[6]  = fmaf(w1.z, v, acc[6]);  acc[7]  = fmaf(w1.w, v, acc[7]);
        acc[8]  = fmaf(w2.x, v, acc[8]);  acc[9]  = fmaf(w2.y, v, acc[9]);
        acc[10] = fmaf(w2.z, v, acc[10]); acc[11] = fmaf(w2.w, v, acc[11]);
        acc[12] = fmaf(w3.x, v, acc[12]); acc[13] = fmaf(w3.y, v, acc[13]);
        acc[14] = fmaf(w3.z, v, acc[14]); acc[15] = fmaf(w3.w, v, acc[15]);
    }

    float* rdst = g_r + (size_t)b * (CRR * HW) + p;
#pragma unroll
    for (int cr = 0; cr < 16; cr++) rdst[cr * HW] = acc[cr];

    // deterministic block reduction of sum / sumsq per channel
    int lane = tid & 31, warp = tid >> 5;
#pragma unroll
    for (int cr = 0; cr < 16; cr++) {
        float s = acc[cr];
        float q = acc[cr] * acc[cr];
#pragma unroll
        for (int off = 16; off; off >>= 1) {
            s += __shfl_down_sync(0xFFFFFFFFu, s, off);
            q += __shfl_down_sync(0xFFFFFFFFu, q, off);
        }
        if (lane == 0) { sm_s[cr][warp] = s; sm_q[cr][warp] = q; }
    }
    __syncthreads();
    if (tid < 16) {
        float s = 0.f, q = 0.f;
#pragma unroll
        for (int w = 0; w < 8; w++) { s += sm_s[tid][w]; q += sm_q[tid][w]; }
        g_psum[tid * STAT_BLOCKS + blockIdx.x] = s;
        g_psq [tid * STAT_BLOCKS + blockIdx.x] = q;
    }
}

// ---------------------------------------------------------------------------
// Kernel D: finalize BN stats -> scale/bias. 1 block, 16 warps (one per cr).
// ---------------------------------------------------------------------------
__global__ void k_bnstats(const float* __restrict__ gamma, const float* __restrict__ beta) {
    int w = threadIdx.x >> 5;     // cr
    int lane = threadIdx.x & 31;
    float s = 0.f, q = 0.f;
    for (int i = lane; i < STAT_BLOCKS; i += 32) {
        s += g_psum[w * STAT_BLOCKS + i];
        q += g_psq [w * STAT_BLOCKS + i];
    }
#pragma unroll
    for (int off = 16; off; off >>= 1) {
        s += __shfl_down_sync(0xFFFFFFFFu, s, off);
        q += __shfl_down_sync(0xFFFFFFFFu, q, off);
    }
    if (lane == 0) {
        const float inv = 1.0f / (float)NPIX;
        float mean = s * inv;
        float var  = q * inv - mean * mean;
        float sc = gamma[w] * rsqrtf(var + 1e-5f);
        g_scale[w] = sc;
        g_bias[w]  = beta[w] - mean * sc;
    }
}

// ---------------------------------------------------------------------------
// Kernel E: fused BN+ReLU -> span GEMM (kern gen) -> involution (49 taps x 4 ch).
// grid (8, 8, B*G), block 256 (16x16 tile). h tile (4 ch packed float4) in shared.
// ---------------------------------------------------------------------------
__global__ __launch_bounds__(256, 2) void k_main(const float* __restrict__ wspan,
                                                 float* __restrict__ out) {
    __shared__ float4 hsh[22 * 22];
    __shared__ float  wsp[49 * 16];
    __shared__ float  ssc[16], sbi[16];

    int tid = threadIdx.x;
    int b = blockIdx.z >> 4;
    int g = blockIdx.z & 15;

    // stage span weights for this group
    const float* wsrc = wspan + g * 49 * 16;
    for (int i = tid; i < 784; i += 256) wsp[i] = wsrc[i];
    if (tid < 16) { ssc[tid] = g_scale[tid]; sbi[tid] = g_bias[tid]; }

    // stage h tile (4 channels of this group, packed) with halo 3
    int y0 = blockIdx.y * 16 - 3, x0 = blockIdx.x * 16 - 3;
    const float* hb = g_h + (size_t)b * CHW + (g * 4) * HW;
    for (int i = tid; i < 484; i += 256) {
        int ly = i / 22, lx = i - ly * 22;
        int yy = y0 + ly, xx = x0 + lx;
        float4 v = make_float4(0.f, 0.f, 0.f, 0.f);
        if ((unsigned)yy < (unsigned)HH && (unsigned)xx < (unsigned)WW) {
            int off = yy * WW + xx;
            v.x = hb[off];
            v.y = hb[off + HW];
            v.z = hb[off + 2 * HW];
            v.w = hb[off + 3 * HW];
        }
        hsh[i] = v;
    }
    __syncthreads();

    int ty = tid >> 4, tx = tid & 15;
    int y = blockIdx.y * 16 + ty, x = blockIdx.x * 16 + tx;

    // normalized + ReLU'd r for this pixel
    const float* rb = g_r + (size_t)b * (CRR * HW) + y * WW + x;
    float rn[16];
#pragma unroll
    for (int cr = 0; cr < 16; cr++)
        rn[cr] = fmaxf(fmaf(rb[cr * HW], ssc[cr], sbi[cr]), 0.f);

    // kernel generation: kern[kk] = sum_cr wsp[kk][cr] * rn[cr]
    float kern[49];
#pragma unroll
    for (int kk = 0; kk < 49; kk++) {
        const float4* w4 = (const float4*)&wsp[kk * 16];
        float4 w0 = w4[0], w1 = w4[1], w2 = w4[2], w3 = w4[3];
        float s;
        s = w0.x * rn[0];
        s = fmaf(w0.y, rn[1],  s);
        s = fmaf(w0.z, rn[2],  s);
        s = fmaf(w0.w, rn[3],  s);
        s = fmaf(w1.x, rn[4],  s);
        s = fmaf(w1.y, rn[5],  s);
        s = fmaf(w1.z, rn[6],  s);
        s = fmaf(w1.w, rn[7],  s);
        s = fmaf(w2.x, rn[8],  s);
        s = fmaf(w2.y, rn[9],  s);
        s = fmaf(w2.z, rn[10], s);
        s = fmaf(w2.w, rn[11], s);
        s = fmaf(w3.x, rn[12], s);
        s = fmaf(w3.y, rn[13], s);
        s = fmaf(w3.z, rn[14], s);
        s = fmaf(w3.w, rn[15], s);
        kern[kk] = s;
    }

    // involution: 49 taps x 4 channels (float4 packed)
    float ax = 0.f, ay = 0.f, az = 0.f, aw = 0.f;
#pragma unroll
    for (int ky = 0; ky < 7; ky++) {
#pragma unroll
        for (int kx = 0; kx < 7; kx++) {
            float4 hv = hsh[(ty + ky) * 22 + (tx + kx)];
            float kw = kern[ky * 7 + kx];
            ax = fmaf(kw, hv.x, ax);
            ay = fmaf(kw, hv.y, ay);
            az = fmaf(kw, hv.z, az);
            aw = fmaf(kw, hv.w, aw);
        }
    }

    float* ob = out + (size_t)b * CHW + (g * 4) * HW + y * WW + x;
    ob[0]      = ax;
    ob[HW]     = ay;
    ob[2 * HW] = az;
    ob[3 * HW] = aw;
}

// ---------------------------------------------------------------------------
extern "C" void kernel_launch(void* const* d_in, const int* in_sizes, int n_in,
                              void* d_out, int out_size) {
    const float* x      = (const float*)d_in[0];   // input  [4,64,128,128]
    const float* w_dw   = (const float*)d_in[1];   // [64,1,3,3]
    const float* w_pw   = (const float*)d_in[2];   // [64,64]
    const float* gamma  = (const float*)d_in[3];   // [16]
    const float* beta   = (const float*)d_in[4];   // [16]
    const float* w_red  = (const float*)d_in[5];   // [16,64]
    const float* w_span = (const float*)d_in[6];   // [784,16]
    float* out = (float*)d_out;

    k_dw<<<4096, 256>>>(x, w_dw);
    k_pw<<<dim3(64, 4), 256>>>(w_pw);
    k_reduce<<<STAT_BLOCKS, 256>>>(x, w_red);
    k_bnstats<<<1, 512>>>(gamma, beta);
    k_main<<<dim3(8, 8, BB * GG), 256>>>(w_span, out);
}

// round 6
// speedup vs baseline: 1.5674x; 1.0019x over previous
#include <cuda_runtime.h>

#define BB 4
#define CC 64
#define HH 128
#define WW 128
#define GG 16
#define KK 7
#define CRR 16
#define HW (HH*WW)            // 16384
#define CHW (CC*HW)           // 1048576
#define NPIX (BB*HW)          // 65536
#define STAT_BLOCKS 256

// Scratch (device globals: allocation-guard safe)
__device__ float g_dw[BB*CHW];            // depthwise output, 16MB
__device__ float g_h [BB*CHW];            // pointwise output (involution "features"), 16MB
__device__ float g_r [BB*CRR*HW];         // reduce output (pre-BN), 4MB
__device__ float g_psum[CRR*STAT_BLOCKS];
__device__ float g_psq [CRR*STAT_BLOCKS];
__device__ float g_scale[CRR];
__device__ float g_bias [CRR];

// ---------------------------------------------------------------------------
// Kernel A: depthwise 3x3 conv, pad 1. One thread = one float4 quad of pixels.
// ---------------------------------------------------------------------------
__global__ void k_dw(const float* __restrict__ x, const float* __restrict__ wdw) {
    int t = blockIdx.x * blockDim.x + threadIdx.x;   // 0 .. 1048575
    int xq = t & 31;            // quad index in row (32 quads of 4)
    int y  = (t >> 5) & 127;
    int c  = (t >> 12) & 63;
    int b  = t >> 18;

    float w[9];
    const float* wp = wdw + c * 9;
#pragma unroll
    for (int i = 0; i < 9; i++) w[i] = __ldg(wp + i);

    float a0 = 0.f, a1 = 0.f, a2 = 0.f, a3 = 0.f;
    const float* base = x + (size_t)(b * 64 + c) * HW;
    int x0 = xq * 4;
#pragma unroll
    for (int dy = -1; dy <= 1; dy++) {
        int yy = y + dy;
        if (yy < 0 || yy >= HH) continue;
        const float* row = base + yy * WW;
        float v[6];
#pragma unroll
        for (int j = 0; j < 6; j++) {
            int xx = x0 - 1 + j;
            v[j] = (xx >= 0 && xx < WW) ? row[xx] : 0.f;
        }
#pragma unroll
        for (int kx = 0; kx < 3; kx++) {
            float wv = w[(dy + 1) * 3 + kx];
            a0 = fmaf(wv, v[kx + 0], a0);
            a1 = fmaf(wv, v[kx + 1], a1);
            a2 = fmaf(wv, v[kx + 2], a2);
            a3 = fmaf(wv, v[kx + 3], a3);
        }
    }
    float4* dst = (float4*)(g_dw + (size_t)(b * 64 + c) * HW + y * WW + x0);
    *dst = make_float4(a0, a1, a2, a3);
}

// ---------------------------------------------------------------------------
// Kernel B: pointwise 1x1, 64->64. Thread = (pixel quad, chunk of 16 outputs).
// grid (64, 4), block 256. Weights staged in shared.
// ---------------------------------------------------------------------------
__global__ void k_pw(const float* __restrict__ wpw) {
    __shared__ float wsh[64 * 64];
    int tid = threadIdx.x;
    for (int i = tid; i < 4096; i += 256) wsh[i] = wpw[i];
    __syncthreads();

    int quad = blockIdx.x * 256 + tid;    // 0..16383
    int oc0  = blockIdx.y * 16;           // output channel base
    int b  = quad >> 12;                  // 4096 quads per image
    int p4 = (quad & 4095) * 4;

    const float* src = g_dw + (size_t)b * CHW + p4;

    float4 acc[16];
#pragma unroll
    for (int o = 0; o < 16; o++) acc[o] = make_float4(0.f, 0.f, 0.f, 0.f);

#pragma unroll 4
    for (int c4 = 0; c4 < 16; c4++) {
        float4 v0 = *(const float4*)(src + (c4 * 4 + 0) * HW);
        float4 v1 = *(const float4*)(src + (c4 * 4 + 1) * HW);
        float4 v2 = *(const float4*)(src + (c4 * 4 + 2) * HW);
        float4 v3 = *(const float4*)(src + (c4 * 4 + 3) * HW);
#pragma unroll
        for (int o = 0; o < 16; o++) {
            float4 wv = *(const float4*)&wsh[(oc0 + o) * 64 + c4 * 4];
            acc[o].x = fmaf(wv.x, v0.x, fmaf(wv.y, v1.x, fmaf(wv.z, v2.x, fmaf(wv.w, v3.x, acc[o].x))));
            acc[o].y = fmaf(wv.x, v0.y, fmaf(wv.y, v1.y, fmaf(wv.z, v2.y, fmaf(wv.w, v3.y, acc[o].y))));
            acc[o].z = fmaf(wv.x, v0.z, fmaf(wv.y, v1.z, fmaf(wv.z, v2.z, fmaf(wv.w, v3.z, acc[o].z))));
            acc[o].w = fmaf(wv.x, v0.w, fmaf(wv.y, v1.w, fmaf(wv.z, v2.w, fmaf(wv.w, v3.w, acc[o].w))));
        }
    }
#pragma unroll
    for (int o = 0; o < 16; o++)
        *(float4*)(g_h + (size_t)b * CHW + (oc0 + o) * HW + p4) = acc[o];
}

// ---------------------------------------------------------------------------
// Kernel C: reduce 64->16 (r) + deterministic per-block BN partial stats.
// One thread per pixel. grid 256, block 256.
// ---------------------------------------------------------------------------
__global__ void k_reduce(const float* __restrict__ x, const float* __restrict__ wred) {
    __shared__ float wt[64 * 16];         // transposed: wt[c*16 + cr]
    __shared__ float sm_s[16][8];
    __shared__ float sm_q[16][8];
    int tid = threadIdx.x;
    for (int i = tid; i < 1024; i += 256) {
        int cr = i >> 6, c = i & 63;
        wt[c * 16 + cr] = wred[i];
    }
    __syncthreads();

    int pix = blockIdx.x * 256 + tid;     // 0..65535
    int b = pix >> 14;
    int p = pix & 16383;
    const float* src = x + (size_t)b * CHW + p;

    float acc[16];
#pragma unroll
    for (int i = 0; i < 16; i++) acc[i] = 0.f;

    for (int c = 0; c < 64; c++) {
        float v = src[c * HW];
        const float4* w4 = (const float4*)&wt[c * 16];
        float4 w0 = w4[0], w1 = w4[1], w2 = w4[2], w3 = w4[3];
        acc[0]  = fmaf(w0.x, v, acc[0]);  acc[1]  = fmaf(w0.y, v, acc[1]);
        acc[2]  = fmaf(w0.z, v, acc[2]);  acc[3]  = fmaf(w0.w, v, acc[3]);
        acc[4]  = fmaf(w1.x, v, acc[4]);  acc[5]  = fmaf(w1.y, v, acc[5]);
        acc[6]  = fmaf(w1.z, v, acc[6]);  acc[7]  = fmaf(w1.w, v, acc[7]);
        acc[8]  = fmaf(w2.x, v, acc[8]);  acc[9]  = fmaf(w2.y, v, acc[9]);
        acc[10] = fmaf(w2.z, v, acc[10]); acc[11] = fmaf(w2.w, v, acc[11]);
        acc[12] = fmaf(w3.x, v, acc[12]); acc[13] = fmaf(w3.y, v, acc[13]);
        acc[14] = fmaf(w3.z, v, acc[14]); acc[15] = fmaf(w3.w, v, acc[15]);
    }

    float* rdst = g_r + (size_t)b * (CRR * HW) + p;
#pragma unroll
    for (int cr = 0; cr < 16; cr++) rdst[cr * HW] = acc[cr];

    // deterministic block reduction of sum / sumsq per channel
    int lane = tid & 31, warp = tid >> 5;
#pragma unroll
    for (int cr = 0; cr < 16; cr++) {
        float s = acc[cr];
        float q = acc[cr] * acc[cr];
#pragma unroll
        for (int off = 16; off; off >>= 1) {
            s += __shfl_down_sync(0xFFFFFFFFu, s, off);
            q += __shfl_down_sync(0xFFFFFFFFu, q, off);
        }
        if (lane == 0) { sm_s[cr][warp] = s; sm_q[cr][warp] = q; }
    }
    __syncthreads();
    if (tid < 16) {
        float s = 0.f, q = 0.f;
#pragma unroll
        for (int w = 0; w < 8; w++) { s += sm_s[tid][w]; q += sm_q[tid][w]; }
        g_psum[tid * STAT_BLOCKS + blockIdx.x] = s;
        g_psq [tid * STAT_BLOCKS + blockIdx.x] = q;
    }
}

// ---------------------------------------------------------------------------
// Kernel D: finalize BN stats -> scale/bias. 1 block, 16 warps (one per cr).
// ---------------------------------------------------------------------------
__global__ void k_bnstats(const float* __restrict__ gamma, const float* __restrict__ beta) {
    int w = threadIdx.x >> 5;     // cr
    int lane = threadIdx.x & 31;
    float s = 0.f, q = 0.f;
    for (int i = lane; i < STAT_BLOCKS; i += 32) {
        s += g_psum[w * STAT_BLOCKS + i];
        q += g_psq [w * STAT_BLOCKS + i];
    }
#pragma unroll
    for (int off = 16; off; off >>= 1) {
        s += __shfl_down_sync(0xFFFFFFFFu, s, off);
        q += __shfl_down_sync(0xFFFFFFFFu, q, off);
    }
    if (lane == 0) {
        const float inv = 1.0f / (float)NPIX;
        float mean = s * inv;
        float var  = q * inv - mean * mean;
        float sc = gamma[w] * rsqrtf(var + 1e-5f);
        g_scale[w] = sc;
        g_bias[w]  = beta[w] - mean * sc;
    }
}

// ---------------------------------------------------------------------------
// Kernel E: fused BN+ReLU -> span GEMM (kern gen) -> involution (49 taps x 4 ch).
// grid (8, 8, B*G), block 256 (16x16 tile). h tile (4 ch packed float4) in shared.
// ---------------------------------------------------------------------------
__global__ __launch_bounds__(256, 2) void k_main(const float* __restrict__ wspan,
                                                 float* __restrict__ out) {
    __shared__ float4 hsh[22 * 22];
    __shared__ float  wsp[49 * 16];
    __shared__ float  ssc[16], sbi[16];

    int tid = threadIdx.x;
    int b = blockIdx.z >> 4;
    int g = blockIdx.z & 15;

    // stage span weights for this group
    const float* wsrc = wspan + g * 49 * 16;
    for (int i = tid; i < 784; i += 256) wsp[i] = wsrc[i];
    if (tid < 16) { ssc[tid] = g_scale[tid]; sbi[tid] = g_bias[tid]; }

    // stage h tile (4 channels of this group, packed) with halo 3
    int y0 = blockIdx.y * 16 - 3, x0 = blockIdx.x * 16 - 3;
    const float* hb = g_h + (size_t)b * CHW + (g * 4) * HW;
    for (int i = tid; i < 484; i += 256) {
        int ly = i / 22, lx = i - ly * 22;
        int yy = y0 + ly, xx = x0 + lx;
        float4 v = make_float4(0.f, 0.f, 0.f, 0.f);
        if ((unsigned)yy < (unsigned)HH && (unsigned)xx < (unsigned)WW) {
            int off = yy * WW + xx;
            v.x = hb[off];
            v.y = hb[off + HW];
            v.z = hb[off + 2 * HW];
            v.w = hb[off + 3 * HW];
        }
        hsh[i] = v;
    }
    __syncthreads();

    int ty = tid >> 4, tx = tid & 15;
    int y = blockIdx.y * 16 + ty, x = blockIdx.x * 16 + tx;

    // normalized + ReLU'd r for this pixel
    const float* rb = g_r + (size_t)b * (CRR * HW) + y * WW + x;
    float rn[16];
#pragma unroll
    for (int cr = 0; cr < 16; cr++)
        rn[cr] = fmaxf(fmaf(rb[cr * HW], ssc[cr], sbi[cr]), 0.f);

    // kernel generation: kern[kk] = sum_cr wsp[kk][cr] * rn[cr]
    float kern[49];
#pragma unroll
    for (int kk = 0; kk < 49; kk++) {
        const float4* w4 = (const float4*)&wsp[kk * 16];
        float4 w0 = w4[0], w1 = w4[1], w2 = w4[2], w3 = w4[3];
        float s;
        s = w0.x * rn[0];
        s = fmaf(w0.y, rn[1],  s);
        s = fmaf(w0.z, rn[2],  s);
        s = fmaf(w0.w, rn[3],  s);
        s = fmaf(w1.x, rn[4],  s);
        s = fmaf(w1.y, rn[5],  s);
        s = fmaf(w1.z, rn[6],  s);
        s = fmaf(w1.w, rn[7],  s);
        s = fmaf(w2.x, rn[8],  s);
        s = fmaf(w2.y, rn[9],  s);
        s = fmaf(w2.z, rn[10], s);
        s = fmaf(w2.w, rn[11], s);
        s = fmaf(w3.x, rn[12], s);
        s = fmaf(w3.y, rn[13], s);
        s = fmaf(w3.z, rn[14], s);
        s = fmaf(w3.w, rn[15], s);
        kern[kk] = s;
    }

    // involution: 49 taps x 4 channels (float4 packed)
    float ax = 0.f, ay = 0.f, az = 0.f, aw = 0.f;
#pragma unroll
    for (int ky = 0; ky < 7; ky++) {
#pragma unroll
        for (int kx = 0; kx < 7; kx++) {
            float4 hv = hsh[(ty + ky) * 22 + (tx + kx)];
            float kw = kern[ky * 7 + kx];
            ax = fmaf(kw, hv.x, ax);
            ay = fmaf(kw, hv.y, ay);
            az = fmaf(kw, hv.z, az);
            aw = fmaf(kw, hv.w, aw);
        }
    }

    float* ob = out + (size_t)b * CHW + (g * 4) * HW + y * WW + x;
    ob[0]      = ax;
    ob[HW]     = ay;
    ob[2 * HW] = az;
    ob[3 * HW] = aw;
}

// ---------------------------------------------------------------------------
extern "C" void kernel_launch(void* const* d_in, const int* in_sizes, int n_in,
                              void* d_out, int out_size) {
    const float* x      = (const float*)d_in[0];   // input  [4,64,128,128]
    const float* w_dw   = (const float*)d_in[1];   // [64,1,3,3]
    const float* w_pw   = (const float*)d_in[2];   // [64,64]
    const float* gamma  = (const float*)d_in[3];   // [16]
    const float* beta   = (const float*)d_in[4];   // [16]
    const float* w_red  = (const float*)d_in[5];   // [16,64]
    const float* w_span = (const float*)d_in[6];   // [784,16]
    float* out = (float*)d_out;

    k_dw<<<4096, 256>>>(x, w_dw);
    k_pw<<<dim3(64, 4), 256>>>(w_pw);
    k_reduce<<<STAT_BLOCKS, 256>>>(x, w_red);
    k_bnstats<<<1, 512>>>(gamma, beta);
    k_main<<<dim3(8, 8, BB * GG), 256>>>(w_span, out);
}